// round 3
// baseline (speedup 1.0000x reference)
#include <cuda_runtime.h>
#include <cstdint>

#define NTOK   524288     // 16*32*32*32
#define BATCH  32
#define ROWS   64         // 2 sides * 32 batch
#define NB1    8192       // buckets: float bits >> 19
#define SMARG  2560u      // sample-rank margin (true ranks: *8)
#define CAPC   98304      // candidate capacity per row
#define CSEL   49152      // smem-resident key cap in k_select

static __device__ __forceinline__ float clampf(float x) {
    return fminf(fmaxf(x, 1e-3f), 0.999f);
}

// ---------------- scratch ----------------
__device__ float        d_tab[2][BATCH][112];    // Ev[16] Et[32] Eh[32] Ew[32]
__device__ int          d_Kc[2];
__device__ unsigned int d_hist[ROWS][NB1];       // sample histogram (2 MB)
__device__ int          d_bHi[ROWS];
__device__ int          d_bLo[ROWS];
__device__ unsigned int d_above[ROWS];
__device__ unsigned int d_candKey[ROWS][CAPC];
__device__ unsigned int d_candIdx[ROWS][CAPC];
__device__ int          d_cc[ROWS];

// ---------------- k_init: zero scratch + (block 0) tables & K ----------------
__global__ void __launch_bounds__(1024) k_init(
    const float* __restrict__ comps, const int* __restrict__ idxp,
    const float* __restrict__ ur_s, const float* __restrict__ ur_t,
    const float* __restrict__ uv_s, const float* __restrict__ ut_s,
    const float* __restrict__ uh_s, const float* __restrict__ uw_s,
    const float* __restrict__ uv_t, const float* __restrict__ ut_t,
    const float* __restrict__ uh_t, const float* __restrict__ uw_t)
{
    int i = blockIdx.x * 1024 + threadIdx.x;
    if (i < ROWS * NB1) ((unsigned int*)d_hist)[i] = 0u;
    if (i < ROWS) { d_cc[i] = 0; d_above[i] = 0u; }

    if (blockIdx.x == 0) {
        int id = idxp[0];
        float ia0 = 1.0f / comps[id*4+0];
        float ia1 = 1.0f / comps[id*4+1];
        float ia2 = 1.0f / comps[id*4+2];
        float ia3 = 1.0f / comps[id*4+3];
        for (int e = threadIdx.x; e < 2*BATCH*112; e += 1024) {
            int side = e / (BATCH*112);
            int rem  = e % (BATCH*112);
            int b = rem / 112;
            int j = rem % 112;
            const float* uv = side ? uv_t : uv_s;
            const float* ut = side ? ut_t : ut_s;
            const float* uh = side ? uh_t : uh_s;
            const float* uw = side ? uw_t : uw_s;
            float val, ia;
            if (j < 16)      { val = uv[b*16 +  j     ]; ia = ia0; }
            else if (j < 48) { val = ut[b*32 + (j-16)]; ia = ia1; }
            else if (j < 80) { val = uh[b*32 + (j-48)]; ia = ia2; }
            else             { val = uw[b*32 + (j-80)]; ia = ia3; }
            d_tab[side][b][j] = powf(clampf(val), ia);
        }
        if (threadIdx.x == 0) d_Kc[0] = (int)(clampf(ur_s[0]) * (float)NTOK);
        if (threadIdx.x == 1) d_Kc[1] = (int)(clampf(ur_t[0]) * (float)NTOK);
    }
}

// ---------------- k_hist: SAMPLED histogram (1/8 of tokens) ----------------
// 8 blocks per row; block handles 256 groups of 32 consecutive tokens (128B line).
// group g in [0,2048): v=g>>7, t=(g>>2)&31, j=g&3, h=(v*3+t*5+j*8)&31.
__global__ void __launch_bounds__(1024) k_hist(const float* __restrict__ u0s,
                                               const float* __restrict__ u0t)
{
    __shared__ unsigned int sh[NB1];
    __shared__ float stab[112];
    int row   = blockIdx.x >> 3;
    int chunk = blockIdx.x & 7;
    int side  = row >> 5, b = row & 31;
    int t = threadIdx.x;
    for (int i = t; i < NB1; i += 1024) sh[i] = 0u;
    if (t < 112) stab[t] = d_tab[side][b][t];
    __syncthreads();

    const float4* src = (const float4*)((side ? u0t : u0s) + (size_t)b * NTOK);

    int g  = chunk * 256 + (t >> 2);     // group id in [0,2048)
    int q  = t & 3;                      // quarter of the group (8 tokens)
    int v  = g >> 7;
    int tt = (g >> 2) & 31;
    int j  = g & 3;
    int h  = (v*3 + tt*5 + j*8) & 31;
    float pre = stab[v] * stab[16+tt] * stab[48+h];
    int base4 = ((((v << 5) | tt) << 5) | h) * 8 + q * 2;
    int w = q * 8;

    float4 a = src[base4];
    float4 c = src[base4 + 1];
    float k0 = clampf(a.x) * pre * stab[80+w+0];
    float k1 = clampf(a.y) * pre * stab[80+w+1];
    float k2 = clampf(a.z) * pre * stab[80+w+2];
    float k3 = clampf(a.w) * pre * stab[80+w+3];
    float k4 = clampf(c.x) * pre * stab[80+w+4];
    float k5 = clampf(c.y) * pre * stab[80+w+5];
    float k6 = clampf(c.z) * pre * stab[80+w+6];
    float k7 = clampf(c.w) * pre * stab[80+w+7];
    atomicAdd(&sh[__float_as_uint(k0) >> 19], 1u);
    atomicAdd(&sh[__float_as_uint(k1) >> 19], 1u);
    atomicAdd(&sh[__float_as_uint(k2) >> 19], 1u);
    atomicAdd(&sh[__float_as_uint(k3) >> 19], 1u);
    atomicAdd(&sh[__float_as_uint(k4) >> 19], 1u);
    atomicAdd(&sh[__float_as_uint(k5) >> 19], 1u);
    atomicAdd(&sh[__float_as_uint(k6) >> 19], 1u);
    atomicAdd(&sh[__float_as_uint(k7) >> 19], 1u);

    __syncthreads();
    for (int i = t; i < NB1; i += 1024)
        if (sh[i]) atomicAdd(&d_hist[row][i], sh[i]);
}

// ---------------- k_scan: parallel suffix scan -> window [bLo, bHi] ----------------
__global__ void __launch_bounds__(1024) k_scan()
{
    __shared__ unsigned int wsum[32];
    __shared__ unsigned int stot;
    int row = blockIdx.x, t = threadIdx.x;
    const unsigned int* hist = d_hist[row];
    unsigned int v[8]; unsigned int s = 0;
    #pragma unroll
    for (int i = 0; i < 8; i++) { v[i] = hist[8191 - (t*8 + i)]; s += v[i]; }
    unsigned int x = s;
    int lane = t & 31, w = t >> 5;
    #pragma unroll
    for (int o = 1; o < 32; o <<= 1) {
        unsigned int y = __shfl_up_sync(0xffffffffu, x, o);
        if (lane >= o) x += y;
    }
    if (lane == 31) wsum[w] = x;
    __syncthreads();
    if (t < 32) {
        unsigned int y = wsum[t], z = y;
        #pragma unroll
        for (int o = 1; o < 32; o <<= 1) {
            unsigned int q = __shfl_up_sync(0xffffffffu, z, o);
            if (t >= o) z += q;
        }
        wsum[t] = z - y;                 // exclusive warp prefix
        if (t == 31) stot = z;
    }
    __syncthreads();
    unsigned int P = wsum[w] + x - s;    // samples strictly above this thread's chunk
    unsigned int K = (unsigned int)d_Kc[row >> 5];
    unsigned int sKt = K >> 3;           // sample fraction exactly 1/8
    unsigned int targHi = (sKt > SMARG) ? (sKt - SMARG) : 0u;
    unsigned int targLo = sKt + SMARG;
    unsigned int total = stot;
    unsigned int cum = P;
    #pragma unroll
    for (int i = 0; i < 8; i++) {
        int bb = 8191 - (t*8 + i);
        unsigned int hv = v[i];
        if (cum <= targHi && cum + hv > targHi) d_bHi[row] = bb;
        if (cum <  targLo && cum + hv >= targLo) d_bLo[row] = bb;
        cum += hv;
    }
    if (t == 0 && targLo > total) d_bLo[row] = 0;
}

// ---------------- k_mask: mask + exact above-count + candidate gather ----------------
__global__ void __launch_bounds__(1024) k_mask(const float* __restrict__ u0s,
                                               const float* __restrict__ u0t,
                                               float* __restrict__ out)
{
    __shared__ float stab[112];
    __shared__ unsigned int s33[33];
    int row   = blockIdx.x >> 2;
    int chunk = blockIdx.x & 3;
    int side  = row >> 5, b = row & 31;
    int t = threadIdx.x;
    if (t < 112) stab[t] = d_tab[side][b][t];
    __syncthreads();

    unsigned int bHi = (unsigned int)d_bHi[row];
    unsigned int bLo = (unsigned int)d_bLo[row];
    unsigned long long hk = ((unsigned long long)(bHi + 1)) << 19;
    float Thif = (hk >= 0x3F800000ull) ? 1.0f : __uint_as_float((unsigned int)hk);
    float Tlof = __uint_as_float(bLo << 19);

    const float4* src = (const float4*)((side ? u0t : u0s) + (size_t)b * NTOK);
    float4* out4 = (float4*)(out + (size_t)row * NTOK);
    int lane = t & 31;
    unsigned int lmask = (1u << lane) - 1u;
    unsigned int nAbove = 0;

    int base4 = chunk * 32768;
    for (int it = 0; it < 32; it++) {
        int idx4 = base4 + it * 1024 + t;
        float4 u = src[idx4];
        int n  = idx4 << 2;
        int v  =  n >> 15;
        int tt = (n >> 10) & 31;
        int h  = (n >> 5)  & 31;
        int w0 =  n & 31;
        float pre = stab[v] * stab[16+tt] * stab[48+h];
        float kf[4];
        kf[0] = clampf(u.x) * pre * stab[80+w0];
        kf[1] = clampf(u.y) * pre * stab[80+w0+1];
        kf[2] = clampf(u.z) * pre * stab[80+w0+2];
        kf[3] = clampf(u.w) * pre * stab[80+w0+3];
        float m[4];
        #pragma unroll
        for (int j = 0; j < 4; j++) {
            bool above = (kf[j] >= Thif);
            m[j] = above ? 1.0f : 0.0f;
            nAbove += above;
            bool cand = (!above) && (kf[j] >= Tlof);
            unsigned int mball = __ballot_sync(0xffffffffu, cand);
            if (mball) {
                int leader = __ffs(mball) - 1;
                int basepos = 0;
                if (lane == leader) basepos = atomicAdd(&d_cc[row], __popc(mball));
                basepos = __shfl_sync(0xffffffffu, basepos, leader);
                if (cand) {
                    int pos = basepos + __popc(mball & lmask);
                    if (pos < CAPC) {
                        d_candKey[row][pos] = __float_as_uint(kf[j]);
                        d_candIdx[row][pos] = (unsigned int)(n + j);
                    }
                }
            }
        }
        out4[idx4] = make_float4(m[0], m[1], m[2], m[3]);
    }

    // exact above-count: block reduce + one global atomic
    unsigned int wv = __reduce_add_sync(0xffffffffu, nAbove);
    if (lane == 0) s33[t >> 5] = wv;
    __syncthreads();
    if (t < 32) {
        unsigned int z = __reduce_add_sync(0xffffffffu, s33[t]);
        if (t == 0) atomicAdd(&d_above[row], z);
    }
}

// ---------------- block reduce helper ----------------
static __device__ __forceinline__ unsigned int blk_reduce_1024(unsigned int v, unsigned int* s33)
{
    unsigned int wv = __reduce_add_sync(0xffffffffu, v);
    int lane = threadIdx.x & 31, w = threadIdx.x >> 5;
    __syncthreads();
    if (lane == 0) s33[w] = wv;
    __syncthreads();
    if (threadIdx.x < 32) {
        unsigned int x = s33[threadIdx.x];
        x = __reduce_add_sync(0xffffffffu, x);
        if (threadIdx.x == 0) s33[32] = x;
    }
    __syncthreads();
    return s33[32];
}

// ---------------- k_select: exact threshold + tie-break among candidates ----------------
extern __shared__ unsigned int dyn_skeys[];
__global__ void __launch_bounds__(1024) k_select(float* __restrict__ out)
{
    __shared__ unsigned int s33[33];
    int row = blockIdx.x;
    int t = threadIdx.x;
    int c = min(d_cc[row], CAPC);
    unsigned int K = (unsigned int)d_Kc[row >> 5];
    unsigned int above = d_above[row];
    int R = (int)K - (int)above;
    if (R <= 0) return;

    const unsigned int* gk = d_candKey[row];
    const unsigned int* gi = d_candIdx[row];
    float* orow = out + (size_t)row * NTOK;

    if (R >= c) {       // take every candidate (guard; window miscalibration)
        for (int i = t; i < c; i += 1024) orow[gi[i]] = 1.0f;
        return;
    }

    bool insm = (c <= CSEL);
    if (insm) {
        for (int i = t; i < c; i += 1024) dyn_skeys[i] = gk[i];
        __syncthreads();
    }
    const unsigned int* kp = insm ? (const unsigned int*)dyn_skeys : gk;

    unsigned int bHi = (unsigned int)d_bHi[row];
    unsigned int bLo = (unsigned int)d_bLo[row];
    unsigned long long hk = ((unsigned long long)(bHi + 1)) << 19;
    unsigned int hiKeyU = (hk >= 0x3F800000ull) ? 0x3F800000u : (unsigned int)hk;

    // largest Tkey with count(key >= Tkey) >= R
    unsigned int lo = bLo << 19;
    unsigned int hi = hiKeyU - 1u;
    while (lo < hi) {
        unsigned int mid = lo + ((hi - lo + 1u) >> 1);
        unsigned int local = 0;
        for (int i = t; i < c; i += 1024) local += (kp[i] >= mid);
        unsigned int cnt = blk_reduce_1024(local, s33);
        if (cnt >= (unsigned int)R) lo = mid; else hi = mid - 1u;
    }
    unsigned int Tkey = lo;

    unsigned int local = 0;
    for (int i = t; i < c; i += 1024) local += (kp[i] > Tkey);
    unsigned int cntGT = blk_reduce_1024(local, s33);
    unsigned int R3 = (unsigned int)R - cntGT;   // >= 1

    // smallest index I* with count(key==Tkey && idx<=I*) >= R3
    unsigned int ilo = 0, ihi = NTOK - 1;
    while (ilo < ihi) {
        unsigned int mid = (ilo + ihi) >> 1;
        unsigned int l2 = 0;
        for (int i = t; i < c; i += 1024)
            if (kp[i] == Tkey) l2 += (gi[i] <= mid);
        unsigned int cnt = blk_reduce_1024(l2, s33);
        if (cnt >= R3) ihi = mid; else ilo = mid + 1u;
    }
    unsigned int Istar = ilo;

    for (int i = t; i < c; i += 1024) {
        unsigned int kb = kp[i];
        if (kb > Tkey)            orow[gi[i]] = 1.0f;
        else if (kb == Tkey) {    if (gi[i] <= Istar) orow[gi[i]] = 1.0f; }
    }
}

// ---------------- launch ----------------
extern "C" void kernel_launch(void* const* d_in, const int* in_sizes, int n_in,
                              void* d_out, int out_size)
{
    const float* comps = (const float*)d_in[0];
    const float* ur_s  = (const float*)d_in[1];
    const float* ur_t  = (const float*)d_in[2];
    const float* u0s   = (const float*)d_in[3];
    const float* u0t   = (const float*)d_in[4];
    const float* uv_s  = (const float*)d_in[5];
    const float* ut_s  = (const float*)d_in[6];
    const float* uh_s  = (const float*)d_in[7];
    const float* uw_s  = (const float*)d_in[8];
    const float* uv_t  = (const float*)d_in[9];
    const float* ut_t  = (const float*)d_in[10];
    const float* uh_t  = (const float*)d_in[11];
    const float* uw_t  = (const float*)d_in[12];
    const int*   idx   = (const int*)d_in[13];
    float* out = (float*)d_out;

    cudaFuncSetAttribute(k_select, cudaFuncAttributeMaxDynamicSharedMemorySize,
                         CSEL * sizeof(unsigned int));

    k_init<<<512, 1024>>>(comps, idx, ur_s, ur_t,
                          uv_s, ut_s, uh_s, uw_s,
                          uv_t, ut_t, uh_t, uw_t);
    k_hist<<<512, 1024>>>(u0s, u0t);
    k_scan<<<64, 1024>>>();
    k_mask<<<256, 1024>>>(u0s, u0t, out);
    k_select<<<64, 1024, CSEL * sizeof(unsigned int)>>>(out);
}

// round 4
// speedup vs baseline: 4.4417x; 4.4417x over previous
#include <cuda_runtime.h>
#include <cstdint>

#define NTOK   524288     // 16*32*32*32
#define BATCH  32
#define ROWS   64         // 2 sides * 32 batch
#define NB1    8192       // buckets: float bits >> 19
#define SMARG  1024u      // sample-rank margin (true ranks: *8)
#define CAPC   49152      // candidate capacity per row (global)
#define BUFCAP 12288      // per-block smem candidate buffer
#define SELCAP 32768      // smem-resident key cap in k_select

static __device__ __forceinline__ float clampf(float x) {
    return fminf(fmaxf(x, 1e-3f), 0.999f);
}

// ---------------- scratch ----------------
__device__ float        d_tab[2][BATCH][112];    // Ev[16] Et[32] Eh[32] Ew[32]
__device__ int          d_Kc[2];
__device__ unsigned int d_hist[ROWS][NB1];       // sample histogram (2 MB)
__device__ int          d_bHi[ROWS];
__device__ int          d_bLo[ROWS];
__device__ unsigned int d_above[ROWS];
__device__ unsigned int d_candKey[ROWS][CAPC];
__device__ unsigned int d_candIdx[ROWS][CAPC];
__device__ unsigned int d_cc[ROWS];

// ---------------- k_init: zero scratch + (block 0) tables & K ----------------
__global__ void __launch_bounds__(1024) k_init(
    const float* __restrict__ comps, const int* __restrict__ idxp,
    const float* __restrict__ ur_s, const float* __restrict__ ur_t,
    const float* __restrict__ uv_s, const float* __restrict__ ut_s,
    const float* __restrict__ uh_s, const float* __restrict__ uw_s,
    const float* __restrict__ uv_t, const float* __restrict__ ut_t,
    const float* __restrict__ uh_t, const float* __restrict__ uw_t)
{
    int i = blockIdx.x * 1024 + threadIdx.x;
    if (i < ROWS * NB1) ((unsigned int*)d_hist)[i] = 0u;
    if (i < ROWS) { d_cc[i] = 0u; d_above[i] = 0u; }

    if (blockIdx.x == 0) {
        int id = idxp[0];
        float ia0 = 1.0f / comps[id*4+0];
        float ia1 = 1.0f / comps[id*4+1];
        float ia2 = 1.0f / comps[id*4+2];
        float ia3 = 1.0f / comps[id*4+3];
        for (int e = threadIdx.x; e < 2*BATCH*112; e += 1024) {
            int side = e / (BATCH*112);
            int rem  = e % (BATCH*112);
            int b = rem / 112;
            int j = rem % 112;
            const float* uv = side ? uv_t : uv_s;
            const float* ut = side ? ut_t : ut_s;
            const float* uh = side ? uh_t : uh_s;
            const float* uw = side ? uw_t : uw_s;
            float val, ia;
            if (j < 16)      { val = uv[b*16 +  j     ]; ia = ia0; }
            else if (j < 48) { val = ut[b*32 + (j-16)]; ia = ia1; }
            else if (j < 80) { val = uh[b*32 + (j-48)]; ia = ia2; }
            else             { val = uw[b*32 + (j-80)]; ia = ia3; }
            d_tab[side][b][j] = powf(clampf(val), ia);
        }
        if (threadIdx.x == 0) d_Kc[0] = (int)(clampf(ur_s[0]) * (float)NTOK);
        if (threadIdx.x == 1) d_Kc[1] = (int)(clampf(ur_t[0]) * (float)NTOK);
    }
}

// ---------------- k_hist: SAMPLED histogram (1/8 of tokens) ----------------
__global__ void __launch_bounds__(1024) k_hist(const float* __restrict__ u0s,
                                               const float* __restrict__ u0t)
{
    __shared__ unsigned int sh[NB1];
    __shared__ float stab[112];
    int row   = blockIdx.x >> 3;
    int chunk = blockIdx.x & 7;
    int side  = row >> 5, b = row & 31;
    int t = threadIdx.x;
    for (int i = t; i < NB1; i += 1024) sh[i] = 0u;
    if (t < 112) stab[t] = d_tab[side][b][t];
    __syncthreads();

    const float4* src = (const float4*)((side ? u0t : u0s) + (size_t)b * NTOK);

    int g  = chunk * 256 + (t >> 2);     // group id in [0,2048)
    int q  = t & 3;
    int v  = g >> 7;
    int tt = (g >> 2) & 31;
    int j  = g & 3;
    int h  = (v*3 + tt*5 + j*8) & 31;
    float pre = stab[v] * stab[16+tt] * stab[48+h];
    int base4 = ((((v << 5) | tt) << 5) | h) * 8 + q * 2;
    int w = q * 8;

    float4 a = src[base4];
    float4 c = src[base4 + 1];
    float k0 = clampf(a.x) * pre * stab[80+w+0];
    float k1 = clampf(a.y) * pre * stab[80+w+1];
    float k2 = clampf(a.z) * pre * stab[80+w+2];
    float k3 = clampf(a.w) * pre * stab[80+w+3];
    float k4 = clampf(c.x) * pre * stab[80+w+4];
    float k5 = clampf(c.y) * pre * stab[80+w+5];
    float k6 = clampf(c.z) * pre * stab[80+w+6];
    float k7 = clampf(c.w) * pre * stab[80+w+7];
    atomicAdd(&sh[__float_as_uint(k0) >> 19], 1u);
    atomicAdd(&sh[__float_as_uint(k1) >> 19], 1u);
    atomicAdd(&sh[__float_as_uint(k2) >> 19], 1u);
    atomicAdd(&sh[__float_as_uint(k3) >> 19], 1u);
    atomicAdd(&sh[__float_as_uint(k4) >> 19], 1u);
    atomicAdd(&sh[__float_as_uint(k5) >> 19], 1u);
    atomicAdd(&sh[__float_as_uint(k6) >> 19], 1u);
    atomicAdd(&sh[__float_as_uint(k7) >> 19], 1u);

    __syncthreads();
    for (int i = t; i < NB1; i += 1024)
        if (sh[i]) atomicAdd(&d_hist[row][i], sh[i]);
}

// ---------------- k_scan: parallel suffix scan -> window [bLo, bHi] ----------------
__global__ void __launch_bounds__(1024) k_scan()
{
    __shared__ unsigned int wsum[32];
    __shared__ unsigned int stot;
    int row = blockIdx.x, t = threadIdx.x;
    const unsigned int* hist = d_hist[row];
    unsigned int v[8]; unsigned int s = 0;
    #pragma unroll
    for (int i = 0; i < 8; i++) { v[i] = hist[8191 - (t*8 + i)]; s += v[i]; }
    unsigned int x = s;
    int lane = t & 31, w = t >> 5;
    #pragma unroll
    for (int o = 1; o < 32; o <<= 1) {
        unsigned int y = __shfl_up_sync(0xffffffffu, x, o);
        if (lane >= o) x += y;
    }
    if (lane == 31) wsum[w] = x;
    __syncthreads();
    if (t < 32) {
        unsigned int y = wsum[t], z = y;
        #pragma unroll
        for (int o = 1; o < 32; o <<= 1) {
            unsigned int q = __shfl_up_sync(0xffffffffu, z, o);
            if (t >= o) z += q;
        }
        wsum[t] = z - y;                 // exclusive warp prefix
        if (t == 31) stot = z;
    }
    __syncthreads();
    unsigned int P = wsum[w] + x - s;    // samples strictly above this thread's chunk
    unsigned int K = (unsigned int)d_Kc[row >> 5];
    unsigned int sKt = K >> 3;
    unsigned int targHi = (sKt > SMARG) ? (sKt - SMARG) : 0u;
    unsigned int targLo = sKt + SMARG;
    unsigned int total = stot;
    unsigned int cum = P;
    #pragma unroll
    for (int i = 0; i < 8; i++) {
        int bb = 8191 - (t*8 + i);
        unsigned int hv = v[i];
        if (cum <= targHi && cum + hv > targHi) d_bHi[row] = bb;
        if (cum <  targLo && cum + hv >= targLo) d_bLo[row] = bb;
        cum += hv;
    }
    if (t == 0 && targLo > total) d_bLo[row] = 0;
}

// ---------------- k_mask: mask + exact above-count + buffered candidate gather ----------------
extern __shared__ unsigned int mbuf[];
__global__ void __launch_bounds__(1024) k_mask(const float* __restrict__ u0s,
                                               const float* __restrict__ u0t,
                                               float* __restrict__ out)
{
    __shared__ float stab[112];
    __shared__ unsigned int s33[33];
    __shared__ unsigned int sCnt, sBase;
    unsigned int* bKey = mbuf;
    unsigned int* bIdx = mbuf + BUFCAP;

    int row   = blockIdx.x >> 2;
    int chunk = blockIdx.x & 3;
    int side  = row >> 5, b = row & 31;
    int t = threadIdx.x;
    if (t < 112) stab[t] = d_tab[side][b][t];
    if (t == 0) sCnt = 0u;
    __syncthreads();

    unsigned int bHi = (unsigned int)d_bHi[row];
    unsigned int bLo = (unsigned int)d_bLo[row];
    unsigned long long hk = ((unsigned long long)(bHi + 1)) << 19;
    float Thif = (hk >= 0x3F800000ull) ? 1.0f : __uint_as_float((unsigned int)hk);
    float Tlof = __uint_as_float(bLo << 19);

    const float4* src = (const float4*)((side ? u0t : u0s) + (size_t)b * NTOK);
    float4* out4 = (float4*)(out + (size_t)row * NTOK);
    int lane = t & 31;
    unsigned int lmask = (1u << lane) - 1u;
    unsigned int nAbove = 0;

    int base4 = chunk * 32768;
    for (int it = 0; it < 32; it++) {
        int idx4 = base4 + it * 1024 + t;
        float4 u = src[idx4];
        int n  = idx4 << 2;
        int v  =  n >> 15;
        int tt = (n >> 10) & 31;
        int h  = (n >> 5)  & 31;
        int w0 =  n & 31;
        float pre = stab[v] * stab[16+tt] * stab[48+h];
        float kf[4];
        kf[0] = clampf(u.x) * pre * stab[80+w0];
        kf[1] = clampf(u.y) * pre * stab[80+w0+1];
        kf[2] = clampf(u.z) * pre * stab[80+w0+2];
        kf[3] = clampf(u.w) * pre * stab[80+w0+3];
        float m[4];
        #pragma unroll
        for (int j = 0; j < 4; j++) {
            bool above = (kf[j] >= Thif);
            m[j] = above ? 1.0f : 0.0f;
            nAbove += above;
            bool cand = (!above) && (kf[j] >= Tlof);
            unsigned int mball = __ballot_sync(0xffffffffu, cand);
            if (mball) {
                int leader = __ffs(mball) - 1;
                unsigned int bp = 0;
                if (lane == leader) bp = atomicAdd(&sCnt, (unsigned int)__popc(mball));
                bp = __shfl_sync(0xffffffffu, bp, leader);
                if (cand) {
                    unsigned int pos = bp + __popc(mball & lmask);
                    if (pos < BUFCAP) {
                        bKey[pos] = __float_as_uint(kf[j]);
                        bIdx[pos] = (unsigned int)(n + j);
                    }
                }
            }
        }
        out4[idx4] = make_float4(m[0], m[1], m[2], m[3]);

        __syncthreads();
        unsigned int cur = sCnt;
        if (cur >= BUFCAP - 4096u) {        // headroom for next iteration (max 4096 appends)
            if (t == 0) sBase = atomicAdd(&d_cc[row], cur);
            __syncthreads();
            unsigned int gb = sBase;
            for (unsigned int i = t; i < cur; i += 1024) {
                unsigned int gpos = gb + i;
                if (gpos < CAPC) { d_candKey[row][gpos] = bKey[i]; d_candIdx[row][gpos] = bIdx[i]; }
            }
            __syncthreads();
            if (t == 0) sCnt = 0u;
            __syncthreads();
        }
    }
    // final flush
    {
        unsigned int cur = sCnt;
        if (cur > 0) {
            if (t == 0) sBase = atomicAdd(&d_cc[row], cur);
            __syncthreads();
            unsigned int gb = sBase;
            for (unsigned int i = t; i < cur; i += 1024) {
                unsigned int gpos = gb + i;
                if (gpos < CAPC) { d_candKey[row][gpos] = bKey[i]; d_candIdx[row][gpos] = bIdx[i]; }
            }
        }
    }

    // exact above-count: block reduce + one global atomic
    unsigned int wv = __reduce_add_sync(0xffffffffu, nAbove);
    if (lane == 0) s33[t >> 5] = wv;
    __syncthreads();
    if (t < 32) {
        unsigned int z = __reduce_add_sync(0xffffffffu, s33[t]);
        if (t == 0) atomicAdd(&d_above[row], z);
    }
}

// ---------------- block reduce helper (fallback path only) ----------------
static __device__ __forceinline__ unsigned int blk_reduce_1024(unsigned int v, unsigned int* s33)
{
    unsigned int wv = __reduce_add_sync(0xffffffffu, v);
    int lane = threadIdx.x & 31, w = threadIdx.x >> 5;
    __syncthreads();
    if (lane == 0) s33[w] = wv;
    __syncthreads();
    if (threadIdx.x < 32) {
        unsigned int x = s33[threadIdx.x];
        x = __reduce_add_sync(0xffffffffu, x);
        if (threadIdx.x == 0) s33[32] = x;
    }
    __syncthreads();
    return s33[32];
}

// ---------------- k_select: radix-descent exact threshold + tie-break ----------------
extern __shared__ unsigned int selk[];
__global__ void __launch_bounds__(1024) k_select(float* __restrict__ out)
{
    __shared__ unsigned int hcnt[1024];
    __shared__ unsigned int wsum[32];
    __shared__ unsigned int sSel, sRnew;
    __shared__ unsigned int eqIdx[2048];
    __shared__ unsigned int eqCnt;
    __shared__ unsigned int sIstar;
    __shared__ unsigned int s33[33];

    int row = blockIdx.x, t = threadIdx.x;
    int c = min((int)d_cc[row], CAPC);
    unsigned int K = (unsigned int)d_Kc[row >> 5];
    unsigned int above = d_above[row];
    int R = (int)K - (int)above;
    const unsigned int* gk = d_candKey[row];
    const unsigned int* gi = d_candIdx[row];
    float* orow = out + (size_t)row * NTOK;
    if (R <= 0) return;
    if (R >= c) { for (int i = t; i < c; i += 1024) orow[gi[i]] = 1.0f; return; }

    bool insm = (c <= SELCAP);
    if (insm) { for (int i = t; i < c; i += 1024) selk[i] = gk[i]; __syncthreads(); }
    const unsigned int* kp = insm ? (const unsigned int*)selk : gk;

    unsigned int bLo = (unsigned int)d_bLo[row], bHi = (unsigned int)d_bHi[row];
    unsigned int base = bLo << 19;
    unsigned long long Wd = ((unsigned long long)(bHi + 1u - bLo)) << 19;
    int sb = (Wd <= 1ull) ? 0 : (64 - __clzll(Wd - 1ull));
    if (sb > 32) sb = 32;
    unsigned int Rcur = (unsigned int)R;

    while (sb > 0) {
        int bits = sb >= 10 ? 10 : sb;
        int shift = sb - bits;
        hcnt[t] = 0u;
        __syncthreads();
        unsigned int spanm = (sb >= 32) ? 0xFFFFFFFFu : ((1u << sb) - 1u);
        for (int i = t; i < c; i += 1024) {
            unsigned int k = kp[i];
            unsigned int d = k - base;
            if (k >= base && d <= spanm) atomicAdd(&hcnt[d >> shift], 1u);
        }
        __syncthreads();
        // incl_top[b] = sum_{u >= b} hcnt[u]; via reversed inclusive scan
        unsigned int x = hcnt[1023 - t];
        unsigned int cb = x;
        int lane = t & 31, w = t >> 5;
        #pragma unroll
        for (int o = 1; o < 32; o <<= 1) {
            unsigned int y = __shfl_up_sync(0xffffffffu, x, o);
            if (lane >= o) x += y;
        }
        if (lane == 31) wsum[w] = x;
        __syncthreads();
        if (t < 32) {
            unsigned int y = wsum[t], z = y;
            #pragma unroll
            for (int o = 1; o < 32; o <<= 1) {
                unsigned int q = __shfl_up_sync(0xffffffffu, z, o);
                if (t >= o) z += q;
            }
            wsum[t] = z - y;
        }
        __syncthreads();
        unsigned int incl = wsum[w] + x;
        unsigned int A = incl - cb;
        if (A < Rcur && Rcur <= incl) { sSel = (unsigned int)(1023 - t); sRnew = Rcur - A; }
        __syncthreads();
        base += sSel << shift;
        Rcur = sRnew;
        sb = shift;
        __syncthreads();
    }
    unsigned int Tkey = base;
    unsigned int R3 = Rcur;   // rank among equal keys (stable by index), >= 1

    if (t == 0) eqCnt = 0u;
    __syncthreads();
    for (int i = t; i < c; i += 1024)
        if (kp[i] == Tkey) {
            unsigned int p = atomicAdd(&eqCnt, 1u);
            if (p < 2048) eqIdx[p] = gi[i];
        }
    __syncthreads();
    unsigned int e = eqCnt;
    unsigned int Istar;
    if (e <= 2048) {
        for (unsigned int j = t; j < e; j += 1024) {
            unsigned int my = eqIdx[j], r = 0;
            for (unsigned int m = 0; m < e; m++) r += (eqIdx[m] < my);
            if (r == R3 - 1u) sIstar = my;
        }
        __syncthreads();
        Istar = sIstar;
    } else {
        unsigned int ilo = 0, ihi = NTOK - 1;
        while (ilo < ihi) {
            unsigned int mid = (ilo + ihi) >> 1;
            unsigned int l2 = 0;
            for (int i = t; i < c; i += 1024)
                if (kp[i] == Tkey) l2 += (gi[i] <= mid);
            unsigned int cnt = blk_reduce_1024(l2, s33);
            if (cnt >= R3) ihi = mid; else ilo = mid + 1u;
        }
        Istar = ilo;
    }

    for (int i = t; i < c; i += 1024) {
        unsigned int kb = kp[i];
        if (kb > Tkey || (kb == Tkey && gi[i] <= Istar)) orow[gi[i]] = 1.0f;
    }
}

// ---------------- launch ----------------
extern "C" void kernel_launch(void* const* d_in, const int* in_sizes, int n_in,
                              void* d_out, int out_size)
{
    const float* comps = (const float*)d_in[0];
    const float* ur_s  = (const float*)d_in[1];
    const float* ur_t  = (const float*)d_in[2];
    const float* u0s   = (const float*)d_in[3];
    const float* u0t   = (const float*)d_in[4];
    const float* uv_s  = (const float*)d_in[5];
    const float* ut_s  = (const float*)d_in[6];
    const float* uh_s  = (const float*)d_in[7];
    const float* uw_s  = (const float*)d_in[8];
    const float* uv_t  = (const float*)d_in[9];
    const float* ut_t  = (const float*)d_in[10];
    const float* uh_t  = (const float*)d_in[11];
    const float* uw_t  = (const float*)d_in[12];
    const int*   idx   = (const int*)d_in[13];
    float* out = (float*)d_out;

    static int attr_done = 0;
    if (!attr_done) {
        cudaFuncSetAttribute(k_mask, cudaFuncAttributeMaxDynamicSharedMemorySize,
                             BUFCAP * 2 * sizeof(unsigned int));
        cudaFuncSetAttribute(k_select, cudaFuncAttributeMaxDynamicSharedMemorySize,
                             SELCAP * sizeof(unsigned int));
        attr_done = 1;
    }

    k_init<<<512, 1024>>>(comps, idx, ur_s, ur_t,
                          uv_s, ut_s, uh_s, uw_s,
                          uv_t, ut_t, uh_t, uw_t);
    k_hist<<<512, 1024>>>(u0s, u0t);
    k_scan<<<64, 1024>>>();
    k_mask<<<256, 1024, BUFCAP * 2 * sizeof(unsigned int)>>>(u0s, u0t, out);
    k_select<<<64, 1024, SELCAP * sizeof(unsigned int)>>>(out);
}